// round 8
// baseline (speedup 1.0000x reference)
#include <cuda_runtime.h>

// Problem constants (fixed shapes for SNNModel_67611375174158)
#define B_DIM   128
#define T_DIM   128
#define BT      (B_DIM * T_DIM)          // 16384 rows
#define NIN     2312                     // 2*34*34
#define NCH     (NIN / 4)                // 578 int4 chunks per row
#define NFULL   (NCH / 32)               // 18 full 32-chunk groups
#define NTAIL   (NCH - NFULL * 32)       // 2 tail chunks
#define NHID    2048
#define NOUT    10
#define ALPHA_F 0.001f

#define NS_OUT  (BT * NOUT)                       // 163840 spike floats
#define TOT_OUT (NS_OUT + NHID * 16 + NOUT * 16)  // 196768 total floats

#define NROWBLK (BT / 8)                          // 2048 row blocks (8 warps each)
#define NSCANBLK 16

// Scratch (no allocations -> __device__ globals)
__device__ unsigned char      g_accB[BT];         // [b*128+t]: acc & 15
__device__ unsigned           g_hasM[4];          // 128-bit has[t] mask (idempotent OR)
__device__ unsigned long long g_A1pack;           // 16 x 4-bit A1 table
__device__ unsigned           g_spk[16];          // spike bitmask per s (10 k-bits)
__device__ unsigned           g_S1[BT / 4];       // packed s1 bytes [b*32 + t/4]
__device__ int                g_cpart[NSCANBLK][32]; // per-block hist partials
__device__ int                g_ok = 1;           // fast-path validity (reset by k_out)

// ---------------------------------------------------------------------------
// Kernel 1: frame scan. One warp per (b,t) row. Inner loop is pure
// XOR/OR word accumulation (values are 0/1 -> bit0 parity == spike parity);
// id nibbles applied post-loop (constant per slot for 128-periodic ids).
// Each block spot-checks one id group -> g_ok. Extra block builds tables.
// ---------------------------------------------------------------------------
__global__ void __launch_bounds__(256, 6) k_rowacc(const int*   __restrict__ frames,
                                                   const int*   __restrict__ ids,
                                                   const int*   __restrict__ nid0,
                                                   const float* __restrict__ vth0,
                                                   const float* __restrict__ map0,
                                                   const float* __restrict__ map1,
                                                   const float* __restrict__ vth1) {
    int tid  = threadIdx.x;
    int lane = tid & 31;

    if (blockIdx.x == NROWBLK) {
        // ---- Table block (cold; register spills OK) ----
        __shared__ int sA1[16];
        if (tid < 16) sA1[tid] = 0;
        __syncthreads();
        int loc[16];
        #pragma unroll
        for (int p = 0; p < 16; p++) loc[p] = 0;
        for (int j = tid; j < NHID; j += 256) {
            int   nid = __ldg(&nid0[j]);
            float vt  = __ldg(&vth0[j]);
            const float4* r = reinterpret_cast<const float4*>(map0 + (size_t)j * 16);
            #pragma unroll
            for (int q = 0; q < 4; q++) {
                float4 mv = __ldg(&r[q]);
                if (mv.x >= vt) loc[q * 4 + 0] ^= nid;
                if (mv.y >= vt) loc[q * 4 + 1] ^= nid;
                if (mv.z >= vt) loc[q * 4 + 2] ^= nid;
                if (mv.w >= vt) loc[q * 4 + 3] ^= nid;
            }
        }
        #pragma unroll
        for (int p = 0; p < 16; p++)
            if (loc[p]) atomicXor(&sA1[p], loc[p]);
        __syncthreads();
        if (tid == 0) {
            unsigned long long pk = 0;
            #pragma unroll
            for (int p = 0; p < 16; p++)
                pk |= (unsigned long long)(sA1[p] & 15) << (4 * p);
            g_A1pack = pk;
        }
        if (tid < 16) {   // spike LUT: plain deterministic stores
            unsigned m = 0;
            #pragma unroll
            for (int k = 0; k < NOUT; k++)
                if (__ldg(&map1[k * 16 + tid]) >= __ldg(&vth1[k])) m |= 1u << k;
            g_spk[tid] = m;
        }
        return;
    }

    // ---- Row blocks ----
    __shared__ unsigned sOr;
    if (tid == 0) sOr = 0;
    __syncthreads();

    int wid = (blockIdx.x * 256 + tid) >> 5;   // row = b*128 + t
    int t   = wid & 127;

    const int4* row4 = reinterpret_cast<const int4*>(frames + (size_t)wid * NIN);
    const int4* ids4 = reinterpret_cast<const int4*>(ids);

    int4 xa = make_int4(0, 0, 0, 0);
    int4 oa = make_int4(0, 0, 0, 0);
    #pragma unroll
    for (int g = 0; g < NFULL; g++) {
        int4 v = __ldg(&row4[g * 32 + lane]);
        xa.x ^= v.x; xa.y ^= v.y; xa.z ^= v.z; xa.w ^= v.w;
        oa.x |= v.x; oa.y |= v.y; oa.z |= v.z; oa.w |= v.w;
    }
    if (lane < NTAIL) {
        int4 v = __ldg(&row4[NFULL * 32 + lane]);
        xa.x ^= v.x; xa.y ^= v.y; xa.z ^= v.z; xa.w ^= v.w;
        oa.x |= v.x; oa.y |= v.y; oa.z |= v.z; oa.w |= v.w;
    }

    // Post-loop: per-slot nibble weights (element i=g*128+4*lane+e; 128%16==0
    // so for 16-periodic-compatible ids the nibble is slot-constant).
    int4 idv = __ldg(&ids4[lane]);
    unsigned n0 = idv.x & 15, n1 = idv.y & 15, n2 = idv.z & 15, n3 = idv.w & 15;
    unsigned a = ((xa.x & 1) ? n0 : 0u) ^ ((xa.y & 1) ? n1 : 0u)
               ^ ((xa.z & 1) ? n2 : 0u) ^ ((xa.w & 1) ? n3 : 0u);
    unsigned anyw = (unsigned)(oa.x | oa.y | oa.z | oa.w);

    unsigned acc  = __reduce_xor_sync(0xFFFFFFFFu, a);
    unsigned anyv = __reduce_or_sync(0xFFFFFFFFu, anyw);

    // Spot-check one id group per block (blocks collectively cover all groups)
    {
        int gchk = blockIdx.x % (NFULL + 1);
        int ok = 1;
        if (gchk < NFULL) {
            int4 w = __ldg(&ids4[gchk * 32 + lane]);
            ok = ((w.x & 15) == (int)n0) & ((w.y & 15) == (int)n1)
               & ((w.z & 15) == (int)n2) & ((w.w & 15) == (int)n3);
        } else if (lane < NTAIL) {
            int4 w = __ldg(&ids4[NFULL * 32 + lane]);
            ok = ((w.x & 15) == (int)n0) & ((w.y & 15) == (int)n1)
               & ((w.z & 15) == (int)n2) & ((w.w & 15) == (int)n3);
        }
        if (!__reduce_and_sync(0xFFFFFFFFu, ok) && lane == 0)
            atomicAnd(&g_ok, 0);
    }

    if (lane == 0) {
        g_accB[(wid >> 7) * 128 + t] = (unsigned char)(acc & 15u);
        if (anyv) atomicOr(&sOr, 1u << (t & 31));
    }
    __syncthreads();
    if (tid == 0 && sOr) atomicOr(&g_hasM[t >> 5], sOr);  // idempotent
}

// ---------------------------------------------------------------------------
// Kernel 2: warp-per-batch prefix-XOR scan. 16 blocks x 8 warps = 128 warps.
// If g_ok==0 (fast path invalid; never for real data), each block first
// recomputes its own batches' acc exactly (self-contained, no cross-block dep).
// ---------------------------------------------------------------------------
__global__ void __launch_bounds__(256) k_scan(const int* __restrict__ frames,
                                              const int* __restrict__ ids) {
    __shared__ unsigned char sDt8[T_DIM];
    __shared__ unsigned char sAm8[T_DIM];
    __shared__ int           sc[32];

    int tid  = threadIdx.x;
    int lane = tid & 31;
    int wrp  = tid >> 5;

    if (tid < 32) sc[tid] = 0;

    // Cold exact-recompute path (correctness fallback; never taken on bench data)
    if (!__ldg(&g_ok)) {
        for (int r = blockIdx.x * 1024 + wrp; r < (blockIdx.x + 1) * 1024; r += 8) {
            const int* rowp = frames + (size_t)r * NIN;
            unsigned x = 0;
            for (int i = lane; i < NIN; i += 32) {
                int v = __ldg(&rowp[i]);
                if (v) x ^= (unsigned)(__ldg(&ids[i]) & 15);
            }
            x = __reduce_xor_sync(0xFFFFFFFFu, x);
            if (lane == 0) g_accB[(r >> 7) * 128 + (r & 127)] = (unsigned char)(x & 15u);
        }
        __syncthreads();
    }

    // Phase C: per-t dt/am from the 128-bit mask (threads 0-127)
    if (tid < 128) {
        unsigned m0 = __ldg(&g_hasM[0]), m1 = __ldg(&g_hasM[1]);
        unsigned m2 = __ldg(&g_hasM[2]), m3 = __ldg(&g_hasM[3]);
        int t = tid, w = t >> 5, bit = t & 31;
        unsigned mw  = (w == 0) ? m0 : (w == 1) ? m1 : (w == 2) ? m2 : m3;
        int active = (mw >> bit) & 1;
        unsigned low = bit ? (mw & ((1u << bit) - 1u)) : 0u;
        unsigned q0 = (w == 0) ? low : m0;
        unsigned q1 = (w == 1) ? low : ((w > 1) ? m1 : 0u);
        unsigned q2 = (w == 2) ? low : ((w > 2) ? m2 : 0u);
        unsigned q3 = (w == 3) ? low : 0u;
        int tl = q3 ? (96 + 31 - __clz(q3))
               : q2 ? (64 + 31 - __clz(q2))
               : q1 ? (32 + 31 - __clz(q1))
               : q0 ? (31 - __clz(q0)) : 0;
        sDt8[t] = (unsigned char)(active ? ((t - tl) & 15) : 0);
        sAm8[t] = (unsigned char)(active ? 0x0F : 0x00);
    }
    __syncthreads();

    int b = blockIdx.x * 8 + wrp;                    // batch for this warp
    unsigned accW = __ldg(&reinterpret_cast<const unsigned*>(g_accB)[b * 32 + lane]);
    unsigned dtW  = reinterpret_cast<const unsigned*>(sDt8)[lane];
    unsigned amW  = reinterpret_cast<const unsigned*>(sAm8)[lane];
    unsigned long long A1p = g_A1pack;

    // s0 pass: x = (acc & am) ^ dt, segment xor, exclusive warp prefix
    unsigned xw = (accW & amW) ^ dtW;
    unsigned fold = xw ^ (xw >> 16);  fold ^= fold >> 8;
    unsigned Xl = fold & 15u;
    unsigned pref = Xl;
    #pragma unroll
    for (int o = 1; o < 32; o <<= 1) {
        unsigned v = __shfl_up_sync(0xFFFFFFFFu, pref, o);
        if (lane >= o) pref ^= v;
    }
    unsigned c = pref ^ Xl;                          // exclusive carry

    unsigned long long h0 = 0, h1 = 0;               // nibble-packed histograms
    unsigned yw = 0;
    #pragma unroll
    for (int j = 0; j < 4; j++) {
        unsigned act = (amW >> (8 * j)) & 1u;
        unsigned xb  = (xw >> (8 * j)) & 15u;
        c ^= xb;                                     // s0 inclusive
        h0 += (unsigned long long)act << (c * 4);
        unsigned a1 = act ? ((unsigned)(A1p >> (c * 4)) & 15u) : 0u;
        unsigned db = (dtW >> (8 * j)) & 15u;
        yw |= (db ^ a1) << (8 * j);
    }

    // s1 pass: prefix over y
    fold = yw ^ (yw >> 16);  fold ^= fold >> 8;
    unsigned Yl = fold & 15u;
    pref = Yl;
    #pragma unroll
    for (int o = 1; o < 32; o <<= 1) {
        unsigned v = __shfl_up_sync(0xFFFFFFFFu, pref, o);
        if (lane >= o) pref ^= v;
    }
    unsigned d = pref ^ Yl;

    unsigned outw = 0;
    #pragma unroll
    for (int j = 0; j < 4; j++) {
        unsigned act = (amW >> (8 * j)) & 1u;
        unsigned yb  = (yw >> (8 * j)) & 15u;
        d ^= yb;                                     // s1 inclusive
        h1 += (unsigned long long)act << (d * 4);
        unsigned sb = act ? d : 0xFFu;
        outw |= sb << (8 * j);
    }
    g_S1[b * 32 + lane] = outw;

    // Histogram reduce: nibble->byte expand + butterfly add
    auto spread = [](unsigned v) -> unsigned long long {
        unsigned long long s = v;
        s = (s | (s << 16)) & 0x0000FFFF0000FFFFULL;
        s = (s | (s << 8))  & 0x00FF00FF00FF00FFULL;
        s = (s | (s << 4))  & 0x0F0F0F0F0F0F0F0FULL;
        return s;
    };
    unsigned long long e0 = spread((unsigned)h0);
    unsigned long long e1 = spread((unsigned)(h0 >> 32));
    unsigned long long f0 = spread((unsigned)h1);
    unsigned long long f1 = spread((unsigned)(h1 >> 32));
    #pragma unroll
    for (int o = 16; o; o >>= 1) {
        e0 += __shfl_xor_sync(0xFFFFFFFFu, e0, o);
        e1 += __shfl_xor_sync(0xFFFFFFFFu, e1, o);
        f0 += __shfl_xor_sync(0xFFFFFFFFu, f0, o);
        f1 += __shfl_xor_sync(0xFFFFFFFFu, f1, o);
    }
    if (lane < 16) {
        unsigned long long c0v = (lane < 8) ? e0 : e1;
        unsigned long long c1v = (lane < 8) ? f0 : f1;
        int sh = (lane & 7) * 8;
        atomicAdd(&sc[lane],      (int)((c0v >> sh) & 255u));
        atomicAdd(&sc[16 + lane], (int)((c1v >> sh) & 255u));
    }
    __syncthreads();
    if (tid < 32) g_cpart[blockIdx.x][tid] = sc[tid];   // plain store, replay-safe
}

// ---------------------------------------------------------------------------
// Kernel 3: output fill (spikes [BT,10], d0 [2048,16], d1 [10,16]).
// Folds the 16 histogram partials in smem; resets g_ok for the next replay.
// ---------------------------------------------------------------------------
__global__ void __launch_bounds__(256) k_out(float*       __restrict__ out,
                                             const float* __restrict__ map0,
                                             const float* __restrict__ map1) {
    __shared__ int sc[32];
    int tid = threadIdx.x;
    if (tid < 32) {
        int v = 0;
        #pragma unroll
        for (int k = 0; k < NSCANBLK; k++) v += __ldg(&g_cpart[k][tid]);
        sc[tid] = v;
    }
    if (blockIdx.x == 0 && tid == 0) g_ok = 1;   // reset for next replay
    __syncthreads();

    int e = blockIdx.x * 256 + tid;
    if (e >= TOT_OUT) return;
    float r;
    if (e < NS_OUT) {
        int bt = e / NOUT;
        int k  = e - bt * NOUT;
        unsigned s = (__ldg(&g_S1[bt >> 2]) >> ((bt & 3) * 8)) & 0xFFu;
        unsigned msk = g_spk[s & 15];
        r = (s != 0xFFu && ((msk >> k) & 1u)) ? 1.0f : 0.0f;
    } else if (e < NS_OUT + NHID * 16) {
        int f = e - NS_OUT;
        int p = f & 15;
        r = ALPHA_F * (float)sc[p] * ((float)p - __ldg(&map0[f]));
    } else {
        int f = e - NS_OUT - NHID * 16;
        int p = f & 15;
        r = ALPHA_F * (float)sc[16 + p] * ((float)p - __ldg(&map1[f]));
    }
    out[e] = r;
}

// ---------------------------------------------------------------------------
// Inputs (metadata order): frames, input_neuron_id, tau0, v_th0, neuron_id0,
// mem_map0, syn_w0, tau1, v_th1, neuron_id1, mem_map1, syn_w1
// ---------------------------------------------------------------------------
extern "C" void kernel_launch(void* const* d_in, const int* in_sizes, int n_in,
                              void* d_out, int out_size) {
    const int*   frames = (const int*)  d_in[0];
    const int*   inid   = (const int*)  d_in[1];
    const float* vth0   = (const float*)d_in[3];
    const int*   nid0   = (const int*)  d_in[4];
    const float* map0   = (const float*)d_in[5];
    const float* vth1   = (const float*)d_in[8];
    const float* map1   = (const float*)d_in[10];

    k_rowacc<<<NROWBLK + 1, 256>>>(frames, inid, nid0, vth0, map0, map1, vth1);
    k_scan<<<NSCANBLK, 256>>>(frames, inid);
    k_out<<<(TOT_OUT + 255) / 256, 256>>>((float*)d_out, map0, map1);
}